// round 2
// baseline (speedup 1.0000x reference)
#include <cuda_runtime.h>
#include <math.h>

// Problem constants
#define NB   32
#define CIN  64
#define COUT 128
#define TT   256
#define VV   25
#define IC   32
#define SLEN (TT*VV)          // 6400 flattened (t,v)
#define EPS  1e-5f

// Scratch (device globals — no allocation allowed)
__device__ float g_z[(size_t)NB*COUT*TT*VV];   // post-bn1-relu activations, 105 MB
__device__ float g_s[NB*IC*VV];                // softmax weights

// ---------------------------------------------------------------------------
// Kernel A: xbar = mean_t(x) ; x2 = w2@xbar + b2 ; s = softmax_v(-x2)
// grid 32 (n), 256 threads
// ---------------------------------------------------------------------------
__global__ void kernelA(const float* __restrict__ x,
                        const float* __restrict__ w2,
                        const float* __restrict__ b2)
{
    const int n = blockIdx.x;
    const int tid = threadIdx.x;
    __shared__ float xbar[CIN*VV];   // 1600
    __shared__ float x2s[IC*VV];     // 800

    for (int idx = tid; idx < CIN*VV; idx += 256) {
        int c = idx / VV, v = idx % VV;
        const float* xp = x + ((size_t)(n*CIN + c)*TT)*VV + v;
        float sum = 0.f;
        for (int t = 0; t < TT; ++t) sum += xp[t*VV];
        xbar[idx] = sum * (1.0f/256.0f);
    }
    __syncthreads();

    for (int idx = tid; idx < IC*VV; idx += 256) {
        int i = idx / VV, v = idx % VV;
        float acc = b2[i];
        for (int c = 0; c < CIN; ++c)
            acc = fmaf(w2[i*CIN + c], xbar[c*VV + v], acc);
        x2s[idx] = acc;
    }
    __syncthreads();

    if (tid < IC) {
        const int i = tid;
        float mx = -1e30f;
        #pragma unroll
        for (int v = 0; v < VV; ++v) mx = fmaxf(mx, -x2s[i*VV + v]);
        float e[VV]; float sum = 0.f;
        #pragma unroll
        for (int v = 0; v < VV; ++v) { e[v] = expf(-x2s[i*VV + v] - mx); sum += e[v]; }
        float inv = 1.0f / sum;
        #pragma unroll
        for (int v = 0; v < VV; ++v) g_s[(n*IC + i)*VV + v] = e[v] * inv;
    }
}

// ---------------------------------------------------------------------------
// Kernel B: per (n, t-tile of 8): 1x1 convs w3/w4/wr from smem x-row,
//   g = <s, x3row>, y2 = A @ x4row, z = relu(bn1(g + y2)) -> g_z
//   res = bnr(wr@x + br) -> d_out (consumed by kernel C)
// grid (32 tgroups, 32 n), 128 threads (thread = output channel o)
// ---------------------------------------------------------------------------
__global__ void __launch_bounds__(128) kernelB(
    const float* __restrict__ x,  const float* __restrict__ Amat,
    const float* __restrict__ w3, const float* __restrict__ b3,
    const float* __restrict__ w4, const float* __restrict__ b4,
    const float* __restrict__ bn1_g, const float* __restrict__ bn1_b,
    const float* __restrict__ bn1_m, const float* __restrict__ bn1_v,
    const float* __restrict__ wr, const float* __restrict__ br,
    const float* __restrict__ bnr_g, const float* __restrict__ bnr_b,
    const float* __restrict__ bnr_m, const float* __restrict__ bnr_v,
    float* __restrict__ res_out)
{
    const int n  = blockIdx.y;
    const int t0 = blockIdx.x * 8;
    const int o  = threadIdx.x;           // 0..127
    const int c32 = o & 31;

    __shared__ float As[VV*VV];   // 625
    __shared__ float ss[IC*VV];   // 800
    __shared__ float xr[CIN*VV];  // 1600

    for (int idx = o; idx < VV*VV; idx += 128) As[idx] = Amat[idx];
    for (int idx = o; idx < IC*VV; idx += 128) ss[idx] = g_s[n*IC*VV + idx];

    const float scale1 = bn1_g[o] * rsqrtf(bn1_v[o] + EPS);
    const float shift1 = bn1_b[o] - bn1_m[o] * scale1;
    const float scaler = bnr_g[o] * rsqrtf(bnr_v[o] + EPS);
    const float shiftr = bnr_b[o] - bnr_m[o] * scaler;
    const float b3o = b3[o], b4o = b4[o], bro = br[o];
    const float* w3p = w3 + o*CIN;
    const float* w4p = w4 + o*CIN;
    const float* wrp = wr + o*CIN;

    for (int tt = 0; tt < 8; ++tt) {
        const int t = t0 + tt;
        __syncthreads();  // also covers As/ss on first iteration
        for (int idx = o; idx < CIN*VV; idx += 128) {
            int c = idx / VV, v = idx % VV;
            xr[idx] = x[((size_t)(n*CIN + c)*TT + t)*VV + v];
        }
        __syncthreads();

        float a3[VV], a4[VV], ar[VV];
        #pragma unroll
        for (int v = 0; v < VV; ++v) { a3[v]=0.f; a4[v]=0.f; ar[v]=0.f; }

        for (int c = 0; c < CIN; ++c) {
            const float w3v = w3p[c], w4v = w4p[c], wrv = wrp[c];
            #pragma unroll
            for (int v = 0; v < VV; ++v) {
                const float xv = xr[c*VV + v];
                a3[v] = fmaf(w3v, xv, a3[v]);
                a4[v] = fmaf(w4v, xv, a4[v]);
                ar[v] = fmaf(wrv, xv, ar[v]);
            }
        }

        // g = b3 + <s_row, a3>   (sum_v s = 1, so b3 folds out)
        float g = b3o;
        const float* srow = &ss[c32*VV];
        #pragma unroll
        for (int v = 0; v < VV; ++v) g = fmaf(srow[v], a3[v], g);
        #pragma unroll
        for (int v = 0; v < VV; ++v) a4[v] += b4o;

        const size_t base = ((size_t)(n*COUT + o)*TT + t)*VV;

        #pragma unroll
        for (int u = 0; u < VV; ++u)
            res_out[base + u] = fmaf(scaler, ar[u] + bro, shiftr);

        #pragma unroll
        for (int u = 0; u < VV; ++u) {
            float y2 = 0.f;
            const float* arow = &As[u*VV];
            #pragma unroll
            for (int v = 0; v < VV; ++v) y2 = fmaf(arow[v], a4[v], y2);
            float z = fmaf(scale1, g + y2, shift1);
            g_z[base + u] = fmaxf(z, 0.f);
        }
    }
}

// ---------------------------------------------------------------------------
// Kernel C: temporal conv as shifted GEMM per n:
//   OUT[o,s] = sum_{i,k} wt[o,i,k] * Z[i, s + 25*(k-4)]  (zero-padded in t)
// then out = relu(bn2(OUT + bt) + res)
// grid (100 s-tiles of 64, 32 n), 128 threads, 8x8 register tile per thread
// ---------------------------------------------------------------------------
#define S_TILE   64
#define ICHUNK   8
#define WSTR     73      // padded (72 used) to break bank conflicts
#define ZSTR     264     // 64 + 200 halo

__global__ void __launch_bounds__(128) kernelC(
    const float* __restrict__ wt, const float* __restrict__ bt,
    const float* __restrict__ bn2_g, const float* __restrict__ bn2_b,
    const float* __restrict__ bn2_m, const float* __restrict__ bn2_v,
    float* __restrict__ out)
{
    const int n  = blockIdx.y;
    const int s0 = blockIdx.x * S_TILE;
    const int tid = threadIdx.x;
    const int tx = tid & 7;     // s sub-tile (8 wide)
    const int ty = tid >> 3;    // o sub-tile (16 groups of 8)

    __shared__ float Ws[COUT*WSTR];     // 128*73*4 = 37376 B
    __shared__ float Zs[ICHUNK*ZSTR];   // 8*264*4  =  8448 B

    float acc[8][8];
    #pragma unroll
    for (int r = 0; r < 8; ++r)
        #pragma unroll
        for (int j = 0; j < 8; ++j) acc[r][j] = 0.f;

    const float* zn = g_z + (size_t)n * COUT * SLEN;

    for (int ic = 0; ic < COUT/ICHUNK; ++ic) {
        __syncthreads();
        // wt chunk: 128 o x 8 i x 9 k
        for (int idx = tid; idx < COUT*ICHUNK*9; idx += 128) {
            int oo = idx / 72, r = idx % 72;
            int ii = r / 9, kk = r % 9;
            Ws[oo*WSTR + r] = wt[(size_t)oo*COUT*9 + (ic*ICHUNK + ii)*9 + kk];
        }
        // z chunk with halo, zero-padded at t boundaries
        for (int idx = tid; idx < ICHUNK*ZSTR; idx += 128) {
            int ii = idx / ZSTR, sl = idx % ZSTR;
            int sg = s0 - 100 + sl;
            Zs[idx] = (sg >= 0 && sg < SLEN)
                      ? zn[(size_t)(ic*ICHUNK + ii)*SLEN + sg] : 0.f;
        }
        __syncthreads();

        for (int i = 0; i < ICHUNK; ++i) {
            #pragma unroll
            for (int k = 0; k < 9; ++k) {
                float zr[8];
                const float* zp = &Zs[i*ZSTR + tx*8 + 25*k];
                #pragma unroll
                for (int j = 0; j < 8; ++j) zr[j] = zp[j];
                #pragma unroll
                for (int r = 0; r < 8; ++r) {
                    const float wv = Ws[(ty*8 + r)*WSTR + i*9 + k];
                    #pragma unroll
                    for (int j = 0; j < 8; ++j)
                        acc[r][j] = fmaf(wv, zr[j], acc[r][j]);
                }
            }
        }
    }

    #pragma unroll
    for (int r = 0; r < 8; ++r) {
        const int o = ty*8 + r;
        const float sc = bn2_g[o] * rsqrtf(bn2_v[o] + EPS);
        const float sh = bn2_b[o] - bn2_m[o] * sc;
        const float bto = bt[o];
        const size_t base = ((size_t)n*COUT + o)*SLEN + s0 + tx*8;
        #pragma unroll
        for (int j = 0; j < 8; ++j) {
            float v = fmaf(sc, acc[r][j] + bto, sh) + out[base + j];  // += residual
            out[base + j] = fmaxf(v, 0.f);
        }
    }
}

// ---------------------------------------------------------------------------
extern "C" void kernel_launch(void* const* d_in, const int* in_sizes, int n_in,
                              void* d_out, int out_size)
{
    const float* x     = (const float*)d_in[0];
    const float* Amat  = (const float*)d_in[1];
    // d_in[2]=w1, d_in[3]=b1 : unused (x1 cancels in softmax)
    const float* w2    = (const float*)d_in[4];
    const float* b2    = (const float*)d_in[5];
    const float* w3    = (const float*)d_in[6];
    const float* b3    = (const float*)d_in[7];
    const float* w4    = (const float*)d_in[8];
    const float* b4    = (const float*)d_in[9];
    const float* bn1_g = (const float*)d_in[10];
    const float* bn1_b = (const float*)d_in[11];
    const float* bn1_m = (const float*)d_in[12];
    const float* bn1_v = (const float*)d_in[13];
    const float* wt    = (const float*)d_in[14];
    const float* bt    = (const float*)d_in[15];
    const float* bn2_g = (const float*)d_in[16];
    const float* bn2_b = (const float*)d_in[17];
    const float* bn2_m = (const float*)d_in[18];
    const float* bn2_v = (const float*)d_in[19];
    const float* wr    = (const float*)d_in[20];
    const float* br    = (const float*)d_in[21];
    const float* bnr_g = (const float*)d_in[22];
    const float* bnr_b = (const float*)d_in[23];
    const float* bnr_m = (const float*)d_in[24];
    const float* bnr_v = (const float*)d_in[25];
    float* out = (float*)d_out;

    kernelA<<<NB, 256>>>(x, w2, b2);
    kernelB<<<dim3(TT/8, NB), 128>>>(x, Amat, w3, b3, w4, b4,
                                     bn1_g, bn1_b, bn1_m, bn1_v,
                                     wr, br, bnr_g, bnr_b, bnr_m, bnr_v,
                                     out);
    kernelC<<<dim3(SLEN/S_TILE, NB), 128>>>(wt, bt,
                                            bn2_g, bn2_b, bn2_m, bn2_v,
                                            out);
}

// round 5
// speedup vs baseline: 2.0476x; 2.0476x over previous
#include <cuda_runtime.h>
#include <cuda_bf16.h>
#include <math.h>
#include <stdint.h>

// Problem constants
#define NB   32
#define CIN  64
#define COUT 128
#define TT   256
#define VV   25
#define IC   32
#define SLEN (TT*VV)          // 6400 flattened (t,v)
#define EPS  1e-5f
#define STILE 128
#define NSTILE (SLEN/STILE)   // 50

// tcgen05 only exists in the arch-feature ('a') compilation pass.
#if defined(__CUDA_ARCH__) && (defined(__CUDA_ARCH_FEAT_SM103_ALL) || defined(__CUDA_ARCH_FEAT_SM100_ALL))
#define HAS_TC 1
#else
#define HAS_TC 0
#endif

// ---------------------------------------------------------------------------
// Device scratch (no allocation allowed). 16B-aligned: we use uint4 accesses.
// ---------------------------------------------------------------------------
__device__ __align__(16) __nv_bfloat16 g_zhi[(size_t)NB*SLEN*COUT];  // z^T [n][s][o] hi
__device__ __align__(16) __nv_bfloat16 g_zlo[(size_t)NB*SLEN*COUT];  // lo residue
__device__ __align__(16) __nv_bfloat16 g_whi[9*COUT*COUT];           // wt [k][o][i] hi
__device__ __align__(16) __nv_bfloat16 g_wlo[9*COUT*COUT];           // lo
__device__ __align__(16) float g_s[NB*IC*VV];                        // softmax weights

// ---------------------------------------------------------------------------
// PTX helpers (gated to the 'a' pass)
// ---------------------------------------------------------------------------
__device__ __forceinline__ uint32_t smem_u32(const void* p) {
    uint32_t a;
    asm("{ .reg .u64 t; cvta.to.shared.u64 t, %1; cvt.u32.u64 %0, t; }"
        : "=r"(a) : "l"(p));
    return a;
}

#if HAS_TC
__device__ __forceinline__ uint32_t elect_one_pred() {
    uint32_t pred;
    asm volatile("{\n\t.reg .pred p;\n\telect.sync _|p, 0xFFFFFFFF;\n\t"
                 "selp.b32 %0, 1, 0, p;\n\t}" : "=r"(pred));
    return pred;
}
#define TCGEN05_ALLOC(smem_addr, nCols) \
    asm volatile("tcgen05.alloc.cta_group::1.sync.aligned.shared::cta.b32 [%0], %1;" \
        :: "r"((uint32_t)(smem_addr)), "r"((uint32_t)(nCols)) : "memory")
#define TCGEN05_DEALLOC(tmem_addr, nCols) \
    asm volatile("tcgen05.dealloc.cta_group::1.sync.aligned.b32 %0, %1;" \
        :: "r"(tmem_addr), "r"((uint32_t)(nCols)))
#define TCGEN05_COMMIT(mbar) \
    asm volatile("tcgen05.commit.cta_group::1.mbarrier::arrive::one.shared::cluster.b64 [%0];" \
        :: "r"((uint32_t)(mbar)) : "memory")
#define TCGEN05_FENCE_AFTER() \
    asm volatile("tcgen05.fence::after_thread_sync;" ::: "memory")
#define TCGEN05_FENCE_BEFORE() \
    asm volatile("tcgen05.fence::before_thread_sync;" ::: "memory")
#define TCGEN05_WAIT_LD() \
    asm volatile("tcgen05.wait::ld.sync.aligned;" ::: "memory")
#define FENCE_PROXY_ASYNC() \
    asm volatile("fence.proxy.async.shared::cta;" ::: "memory")
#define MBARRIER_INIT(mbar, cnt) \
    asm volatile("mbarrier.init.shared.b64 [%0], %1;" \
        :: "r"((uint32_t)(mbar)), "r"((uint32_t)(cnt)) : "memory")
#define MBARRIER_INVAL(mbar) \
    asm volatile("mbarrier.inval.shared.b64 [%0];" :: "r"((uint32_t)(mbar)) : "memory")
#define MBARRIER_WAIT_PARITY(mbar, phase) do { \
    uint32_t _m = (uint32_t)(mbar); uint32_t _p = (uint32_t)(phase); uint32_t _d; \
    asm volatile("{\n\t.reg .pred p;\n\t" \
        "mbarrier.try_wait.parity.acquire.cta.shared::cta.b64 p, [%1], %2;\n\t" \
        "selp.b32 %0, 1, 0, p;\n\t}" : "=r"(_d) : "r"(_m), "r"(_p) : "memory"); \
    if (!_d) { \
        asm volatile("{\n\t.reg .pred P1;\n\t" \
            "WAIT_LOOP_%=:\n\t" \
            "mbarrier.try_wait.parity.acquire.cta.shared::cta.b64 P1, [%0], %1, 0x989680;\n\t" \
            "@P1 bra.uni WAIT_DONE_%=;\n\t" \
            "bra.uni WAIT_LOOP_%=;\n\t" \
            "WAIT_DONE_%=:\n\t}" :: "r"(_m), "r"(_p) : "memory"); \
    } \
} while (0)
#define TCGEN05_LD_32X32B_X32(r, tmem_addr) \
    asm volatile("tcgen05.ld.sync.aligned.32x32b.x32.b32 " \
        "{%0, %1, %2, %3, %4, %5, %6, %7, " \
        " %8, %9, %10, %11, %12, %13, %14, %15, " \
        " %16, %17, %18, %19, %20, %21, %22, %23, " \
        " %24, %25, %26, %27, %28, %29, %30, %31}, [%32];" \
        : "=r"((r)[0]),  "=r"((r)[1]),  "=r"((r)[2]),  "=r"((r)[3]), \
          "=r"((r)[4]),  "=r"((r)[5]),  "=r"((r)[6]),  "=r"((r)[7]), \
          "=r"((r)[8]),  "=r"((r)[9]),  "=r"((r)[10]), "=r"((r)[11]), \
          "=r"((r)[12]), "=r"((r)[13]), "=r"((r)[14]), "=r"((r)[15]), \
          "=r"((r)[16]), "=r"((r)[17]), "=r"((r)[18]), "=r"((r)[19]), \
          "=r"((r)[20]), "=r"((r)[21]), "=r"((r)[22]), "=r"((r)[23]), \
          "=r"((r)[24]), "=r"((r)[25]), "=r"((r)[26]), "=r"((r)[27]), \
          "=r"((r)[28]), "=r"((r)[29]), "=r"((r)[30]), "=r"((r)[31]) \
        : "r"(tmem_addr))

// SW128 K-major smem descriptor (verified: LBO=1, SBO=64, layout=2, v1)
static constexpr uint64_t DESC_BASE_SW128 =
    (uint64_t(2) << 61) | (uint64_t(1) << 46) | (uint64_t(64) << 32) | (uint64_t(1) << 16);
__device__ __forceinline__ uint64_t make_desc(uint32_t addr) {
    return DESC_BASE_SW128 | ((uint64_t)(addr >> 4) & 0x3FFF);
}
// idesc kind::f16: F32 accum (1<<4), BF16 A (1<<7), BF16 B (1<<10),
// N=128 -> 16<<17, M=128 -> 8<<24
#define MMA_IDESC 0x8200490u

__device__ __forceinline__ void mma_f16_ss(uint32_t d, uint64_t ad, uint64_t bd,
                                           uint32_t idesc, bool en) {
    uint32_t e = en ? 1u : 0u, z = 0u;
    asm volatile("{\n\t.reg .pred p;\n\tsetp.ne.u32 p, %5, 0;\n\t"
        "tcgen05.mma.cta_group::1.kind::f16 [%0], %1, %2, %3, {%4, %4, %4, %4}, p;\n\t}"
        :: "r"(d), "l"(ad), "l"(bd), "r"(idesc), "r"(z), "r"(e) : "memory");
}
#endif  // HAS_TC

#define SWZ128(x) ((x) ^ (((x) >> 3) & 0x70))

// ---------------------------------------------------------------------------
// Kernel W-prep: wt[o][i][k] fp32 -> g_whi/g_wlo[k][o][i] bf16 split
// ---------------------------------------------------------------------------
__global__ void kernelW(const float* __restrict__ wt)
{
    int idx = blockIdx.x * 256 + threadIdx.x;
    if (idx >= 9*COUT*COUT) return;
    int k = idx / (COUT*COUT);
    int r = idx % (COUT*COUT);
    int o = r / COUT, i = r % COUT;
    float w = wt[((size_t)o*COUT + i)*9 + k];
    __nv_bfloat16 h = __float2bfloat16(w);
    g_whi[idx] = h;
    g_wlo[idx] = __float2bfloat16(w - __bfloat162float(h));
}

// ---------------------------------------------------------------------------
// Kernel A: xbar = mean_t(x) ; x2 = w2@xbar + b2 ; s = softmax_v(-x2)
// ---------------------------------------------------------------------------
__global__ void kernelA(const float* __restrict__ x,
                        const float* __restrict__ w2,
                        const float* __restrict__ b2)
{
    const int n = blockIdx.x;
    const int tid = threadIdx.x;
    __shared__ float xbar[CIN*VV];
    __shared__ float x2s[IC*VV];

    for (int idx = tid; idx < CIN*VV; idx += 256) {
        int c = idx / VV, v = idx % VV;
        const float* xp = x + ((size_t)(n*CIN + c)*TT)*VV + v;
        float sum = 0.f;
        for (int t = 0; t < TT; ++t) sum += xp[t*VV];
        xbar[idx] = sum * (1.0f/256.0f);
    }
    __syncthreads();
    for (int idx = tid; idx < IC*VV; idx += 256) {
        int i = idx / VV, v = idx % VV;
        float acc = b2[i];
        for (int c = 0; c < CIN; ++c)
            acc = fmaf(w2[i*CIN + c], xbar[c*VV + v], acc);
        x2s[idx] = acc;
    }
    __syncthreads();
    if (tid < IC) {
        const int i = tid;
        float mx = -1e30f;
        #pragma unroll
        for (int v = 0; v < VV; ++v) mx = fmaxf(mx, -x2s[i*VV + v]);
        float e[VV]; float sum = 0.f;
        #pragma unroll
        for (int v = 0; v < VV; ++v) { e[v] = expf(-x2s[i*VV + v] - mx); sum += e[v]; }
        float inv = 1.0f / sum;
        #pragma unroll
        for (int v = 0; v < VV; ++v) g_s[(n*IC + i)*VV + v] = e[v] * inv;
    }
}

// ---------------------------------------------------------------------------
// Kernel B: 1x1 convs + graph mixes + bn1/relu -> z (bf16 hi/lo, transposed),
//           residual bnr -> d_out
// ---------------------------------------------------------------------------
__global__ void __launch_bounds__(128) kernelB(
    const float* __restrict__ x,  const float* __restrict__ Amat,
    const float* __restrict__ w3, const float* __restrict__ b3,
    const float* __restrict__ w4, const float* __restrict__ b4,
    const float* __restrict__ bn1_g, const float* __restrict__ bn1_b,
    const float* __restrict__ bn1_m, const float* __restrict__ bn1_v,
    const float* __restrict__ wr, const float* __restrict__ br,
    const float* __restrict__ bnr_g, const float* __restrict__ bnr_b,
    const float* __restrict__ bnr_m, const float* __restrict__ bnr_v,
    float* __restrict__ res_out)
{
    const int n  = blockIdx.y;
    const int t0 = blockIdx.x * 8;
    const int o  = threadIdx.x;           // 0..127
    const int c32 = o & 31;

    __shared__ float As[VV*VV];
    __shared__ float ss[IC*VV];
    __shared__ float xr[CIN*VV];

    for (int idx = o; idx < VV*VV; idx += 128) As[idx] = Amat[idx];
    for (int idx = o; idx < IC*VV; idx += 128) ss[idx] = g_s[n*IC*VV + idx];

    const float scale1 = bn1_g[o] * rsqrtf(bn1_v[o] + EPS);
    const float shift1 = bn1_b[o] - bn1_m[o] * scale1;
    const float scaler = bnr_g[o] * rsqrtf(bnr_v[o] + EPS);
    const float shiftr = bnr_b[o] - bnr_m[o] * scaler;
    const float b3o = b3[o], b4o = b4[o], bro = br[o];
    const float* w3p = w3 + o*CIN;
    const float* w4p = w4 + o*CIN;
    const float* wrp = wr + o*CIN;

    for (int tt = 0; tt < 8; ++tt) {
        const int t = t0 + tt;
        __syncthreads();
        for (int idx = o; idx < CIN*VV; idx += 128) {
            int c = idx / VV, v = idx % VV;
            xr[idx] = x[((size_t)(n*CIN + c)*TT + t)*VV + v];
        }
        __syncthreads();

        float a3[VV], a4[VV], ar[VV];
        #pragma unroll
        for (int v = 0; v < VV; ++v) { a3[v]=0.f; a4[v]=0.f; ar[v]=0.f; }

        for (int c = 0; c < CIN; ++c) {
            const float w3v = w3p[c], w4v = w4p[c], wrv = wrp[c];
            #pragma unroll
            for (int v = 0; v < VV; ++v) {
                const float xv = xr[c*VV + v];
                a3[v] = fmaf(w3v, xv, a3[v]);
                a4[v] = fmaf(w4v, xv, a4[v]);
                ar[v] = fmaf(wrv, xv, ar[v]);
            }
        }

        float g = b3o;
        const float* srow = &ss[c32*VV];
        #pragma unroll
        for (int v = 0; v < VV; ++v) g = fmaf(srow[v], a3[v], g);
        #pragma unroll
        for (int v = 0; v < VV; ++v) a4[v] += b4o;

        const size_t rbase = ((size_t)(n*COUT + o)*TT + t)*VV;
        #pragma unroll
        for (int u = 0; u < VV; ++u)
            res_out[rbase + u] = fmaf(scaler, ar[u] + bro, shiftr);

        const size_t zbase = ((size_t)n*SLEN + t*VV)*COUT + o;
        #pragma unroll
        for (int u = 0; u < VV; ++u) {
            float y2 = 0.f;
            const float* arow = &As[u*VV];
            #pragma unroll
            for (int v = 0; v < VV; ++v) y2 = fmaf(arow[v], a4[v], y2);
            float z = fmaxf(fmaf(scale1, g + y2, shift1), 0.f);
            __nv_bfloat16 zh = __float2bfloat16(z);
            float zr = z - __bfloat162float(zh);
            g_zhi[zbase + (size_t)u*COUT] = zh;
            g_zlo[zbase + (size_t)u*COUT] = __float2bfloat16(zr);
        }
    }
}

// ---------------------------------------------------------------------------
// Kernel C: temporal conv D[s,o] = sum_{k,i} Z[s+25(k-4), i] * Wk[o, i]
// tcgen05 bf16x3 GEMM on 'a' pass; FFMA tile fallback otherwise.
// grid (50 s-tiles, 32 n), 256 threads.
// ---------------------------------------------------------------------------
#define SM_TMEM  0
#define SM_MBAR  8
#define SM_SC    16
#define SM_SH    528
#define SM_A_HI  2048
#define SM_A_LO  (SM_A_HI + 32768)
#define SM_B_HI  (SM_A_LO + 32768)
#define SM_B_LO  (SM_B_HI + 32768)
#define SMEM_C_TOTAL 137216   // max(tensor path 133120, fallback 2048+2*132*128*4)

__global__ void __launch_bounds__(256) kernelC(
    const float* __restrict__ bt,
    const float* __restrict__ bn2_g, const float* __restrict__ bn2_b,
    const float* __restrict__ bn2_m, const float* __restrict__ bn2_v,
    float* __restrict__ out)
{
    extern __shared__ char smem[];
    const int n  = blockIdx.y;
    const int s0 = blockIdx.x * STILE;
    const int tid = threadIdx.x;

    // fused bn2 scale/shift (shift absorbs bt)
    if (tid < COUT) {
        float sc = bn2_g[tid] * rsqrtf(bn2_v[tid] + EPS);
        float sh = bn2_b[tid] - bn2_m[tid] * sc;
        ((float*)(smem + SM_SC))[tid] = sc;
        ((float*)(smem + SM_SH))[tid] = fmaf(sc, bt[tid], sh);
    }

    const __nv_bfloat16* zh = g_zhi + (size_t)n * SLEN * COUT;
    const __nv_bfloat16* zl = g_zlo + (size_t)n * SLEN * COUT;

#if HAS_TC
    // ------------------------- tcgen05 path -------------------------
    const uint32_t sb = smem_u32(smem);
    const int wid = tid >> 5;
    const int lane = tid & 31;

    // Only warp 0 allocates; NOBODY relinquishes (avoids permit race).
    if (wid == 0) { TCGEN05_ALLOC(sb + SM_TMEM, 512); }
    if (tid == 0) MBARRIER_INIT(sb + SM_MBAR, 1);
    __syncthreads();
    uint32_t tmem;
    asm volatile("ld.shared.b32 %0, [%1];" : "=r"(tmem) : "r"(sb + SM_TMEM));

    for (int k = 0; k < 9; ++k) {
        if (k > 0) MBARRIER_WAIT_PARITY(sb + SM_MBAR, (k - 1) & 1);

        // A (Z tile, shifted, OOB -> 0): 128 s-rows x 128 i, hi+lo
        const int sbase = s0 + 25*k - 100;
        for (int idx = tid; idx < 2048; idx += 256) {
            const int row = idx >> 4, c = idx & 15;
            const int sg = sbase + row;
            uint4 vh = make_uint4(0,0,0,0), vl = make_uint4(0,0,0,0);
            if ((unsigned)sg < (unsigned)SLEN) {
                vh = *((const uint4*)(zh + (size_t)sg * COUT) + c);
                vl = *((const uint4*)(zl + (size_t)sg * COUT) + c);
            }
            const uint32_t so = ((c >> 3) << 14) + SWZ128((row << 7) + ((c & 7) << 4));
            *(uint4*)(smem + SM_A_HI + so) = vh;
            *(uint4*)(smem + SM_A_LO + so) = vl;
        }
        // B (W tap k): 128 o x 128 i, hi+lo
        const uint4* wh = (const uint4*)(g_whi + (size_t)k * COUT * COUT);
        const uint4* wl = (const uint4*)(g_wlo + (size_t)k * COUT * COUT);
        for (int idx = tid; idx < 2048; idx += 256) {
            const int row = idx >> 4, c = idx & 15;
            const uint32_t so = ((c >> 3) << 14) + SWZ128((row << 7) + ((c & 7) << 4));
            *(uint4*)(smem + SM_B_HI + so) = wh[idx];
            *(uint4*)(smem + SM_B_LO + so) = wl[idx];
        }
        FENCE_PROXY_ASYNC();
        __syncthreads();

        if (wid == 0) {
            TCGEN05_FENCE_AFTER();
            if (elect_one_pred()) {
                const uint32_t AO[3] = { SM_A_HI, SM_A_LO, SM_A_HI };
                const uint32_t BO[3] = { SM_B_HI, SM_B_HI, SM_B_LO };
                #pragma unroll
                for (int c3 = 0; c3 < 3; ++c3) {
                    #pragma unroll
                    for (int pl = 0; pl < 2; ++pl) {
                        uint64_t ad = make_desc(sb + AO[c3] + (pl << 14));
                        uint64_t bd = make_desc(sb + BO[c3] + (pl << 14));
                        #pragma unroll
                        for (int ks = 0; ks < 4; ++ks) {
                            const bool en = !(k == 0 && c3 == 0 && pl == 0 && ks == 0);
                            mma_f16_ss(tmem, ad + ks*2, bd + ks*2, MMA_IDESC, en);
                        }
                    }
                }
                TCGEN05_COMMIT(sb + SM_MBAR);
            }
        }
    }

    MBARRIER_WAIT_PARITY(sb + SM_MBAR, 0);   // 9th commit -> parity 8&1 = 0
    TCGEN05_FENCE_AFTER();

    if (wid < 4) {
        const int srow = s0 + wid * 32 + lane;
        const float* scs = (const float*)(smem + SM_SC);
        const float* shs = (const float*)(smem + SM_SH);
        #pragma unroll
        for (int cb = 0; cb < 128; cb += 32) {
            uint32_t r[32];
            TCGEN05_LD_32X32B_X32(r, tmem + cb);
            TCGEN05_WAIT_LD();
            #pragma unroll
            for (int j = 0; j < 32; ++j) {
                const int o = cb + j;
                const size_t base = ((size_t)(n*COUT + o)) * SLEN + srow;
                float v = fmaf(scs[o], __uint_as_float(r[j]), shs[o]) + out[base];
                out[base] = fmaxf(v, 0.f);
            }
        }
        TCGEN05_FENCE_BEFORE();
    }

    __syncthreads();
    if (tid == 0) MBARRIER_INVAL(sb + SM_MBAR);
    __syncthreads();
    if (wid == 0) TCGEN05_DEALLOC(tmem, 512);
#else
    // ------------------------- FFMA fallback -------------------------
    __syncthreads();
    const int tx = tid & 15, ty = tid >> 4;   // 16x16 threads, 8x8 tile each
    float* Zs = (float*)(smem + 2048);                 // [i][s] stride 132
    float* Ws = (float*)(smem + 2048 + 132*128*4);     // [i][o] stride 132
    float acc[8][8];
    #pragma unroll
    for (int r = 0; r < 8; ++r)
        #pragma unroll
        for (int j = 0; j < 8; ++j) acc[r][j] = 0.f;

    for (int k = 0; k < 9; ++k) {
        __syncthreads();
        const int sbase = s0 + 25*k - 100;
        for (int idx = tid; idx < 128*128; idx += 256) {
            const int row = idx >> 7, i = idx & 127;
            const int sg = sbase + row;
            float z = 0.f;
            if ((unsigned)sg < (unsigned)SLEN)
                z = __bfloat162float(zh[(size_t)sg*COUT + i])
                  + __bfloat162float(zl[(size_t)sg*COUT + i]);
            Zs[i*132 + row] = z;
            const size_t wb = ((size_t)k*COUT + row)*COUT + i;
            Ws[i*132 + row] = __bfloat162float(g_whi[wb]) + __bfloat162float(g_wlo[wb]);
        }
        __syncthreads();
        for (int i = 0; i < 128; ++i) {
            float zr[8], wv[8];
            #pragma unroll
            for (int j = 0; j < 8; ++j) zr[j] = Zs[i*132 + tx*8 + j];
            #pragma unroll
            for (int r = 0; r < 8; ++r) wv[r] = Ws[i*132 + ty*8 + r];
            #pragma unroll
            for (int r = 0; r < 8; ++r)
                #pragma unroll
                for (int j = 0; j < 8; ++j)
                    acc[r][j] = fmaf(wv[r], zr[j], acc[r][j]);
        }
    }
    const float* scs = (const float*)(smem + SM_SC);
    const float* shs = (const float*)(smem + SM_SH);
    #pragma unroll
    for (int r = 0; r < 8; ++r) {
        const int o = ty*8 + r;
        const size_t base = ((size_t)(n*COUT + o))*SLEN + s0 + tx*8;
        #pragma unroll
        for (int j = 0; j < 8; ++j) {
            float v = fmaf(scs[o], acc[r][j], shs[o]) + out[base + j];
            out[base + j] = fmaxf(v, 0.f);
        }
    }
#endif
}

// ---------------------------------------------------------------------------
extern "C" void kernel_launch(void* const* d_in, const int* in_sizes, int n_in,
                              void* d_out, int out_size)
{
    const float* x     = (const float*)d_in[0];
    const float* Amat  = (const float*)d_in[1];
    const float* w2    = (const float*)d_in[4];
    const float* b2    = (const float*)d_in[5];
    const float* w3    = (const float*)d_in[6];
    const float* b3    = (const float*)d_in[7];
    const float* w4    = (const float*)d_in[8];
    const float* b4    = (const float*)d_in[9];
    const float* bn1_g = (const float*)d_in[10];
    const float* bn1_b = (const float*)d_in[11];
    const float* bn1_m = (const float*)d_in[12];
    const float* bn1_v = (const float*)d_in[13];
    const float* wt    = (const float*)d_in[14];
    const float* bt    = (const float*)d_in[15];
    const float* bn2_g = (const float*)d_in[16];
    const float* bn2_b = (const float*)d_in[17];
    const float* bn2_m = (const float*)d_in[18];
    const float* bn2_v = (const float*)d_in[19];
    const float* wr    = (const float*)d_in[20];
    const float* br    = (const float*)d_in[21];
    const float* bnr_g = (const float*)d_in[22];
    const float* bnr_b = (const float*)d_in[23];
    const float* bnr_m = (const float*)d_in[24];
    const float* bnr_v = (const float*)d_in[25];
    float* out = (float*)d_out;

    cudaFuncSetAttribute(kernelC, cudaFuncAttributeMaxDynamicSharedMemorySize,
                         SMEM_C_TOTAL);

    kernelW<<<(9*COUT*COUT + 255)/256, 256>>>(wt);
    kernelA<<<NB, 256>>>(x, w2, b2);
    kernelB<<<dim3(TT/8, NB), 128>>>(x, Amat, w3, b3, w4, b4,
                                     bn1_g, bn1_b, bn1_m, bn1_v,
                                     wr, br, bnr_g, bnr_b, bnr_m, bnr_v,
                                     out);
    kernelC<<<dim3(NSTILE, NB), 256, SMEM_C_TOTAL>>>(bt, bn2_g, bn2_b,
                                                     bn2_m, bn2_v, out);
}